// round 12
// baseline (speedup 1.0000x reference)
#include <cuda_runtime.h>
#include <cstdint>

// Problem constants
#define C_    32
#define S_    9
#define H_    192
#define W_    256
#define G_    8
#define NSRC  8

#define WS    (W_*S_)        // 2304
#define HWS   (H_*WS)        // 442368
#define CHWS  (C_*HWS)       // 14155776
#define HWS4  (HWS>>2)       // 110592
#define CHWS4 (CHWS>>2)      // 3538944

// ===========================================================================
// Fused kernel, register-resident ref.
// Warp tile = 4 pixels x 32 channels. Block = 4 warps. Per warp: only TWO
// smem ring slots (ref lives in registers). Lane map: px=lane>>3, q8=lane&7.
// Each lane owns ref rows c = 8co+q8 (co=0..3) at its pixel, 9 shifts each.
// Attention is computed warp-locally via shfl gathers (no smem scratch).
// ===========================================================================
#define WPX   4
#define NW    4
#define B_TW  (WPX*NW)       // 16 pixels per block
#define CROW  36             // floats per channel per warp tile (4 px * 9)
#define SLOT  (C_*CROW)      // 1152 floats
#define WARPF (2*SLOT)       // 2 ring slots

#define OFF_WPD (NW*WARPF)           // WpD[d*33+c] : 1056
#define OFF_BP  (OFF_WPD+1056)       // 32
#define SMEM_FLOATS (OFF_BP+32)      // 10304 floats
#define SMEM_BYTES  (SMEM_FLOATS*4)  // 41216 B -> 5 blocks/SM

__device__ __forceinline__ void cp16(float* dst, const float4* src) {
    uint32_t s = (uint32_t)__cvta_generic_to_shared(dst);
    asm volatile("cp.async.cg.shared.global [%0], [%1], 16;\n" :: "r"(s), "l"(src));
}
__device__ __forceinline__ void cp_commit() { asm volatile("cp.async.commit_group;\n" ::); }
__device__ __forceinline__ void cp_wait1()  { asm volatile("cp.async.wait_group 1;\n" ::); }
__device__ __forceinline__ void cp_wait0()  { asm volatile("cp.async.wait_group 0;\n" ::); }

// Stage one warp tile: 288 float4 (32 ch x 9 f4), 9 per lane, linear smem.
__device__ __forceinline__ void stage_tile(float* dst, const float4* gbase, int lane) {
    #pragma unroll
    for (int i = 0; i < 9; i++) {
        int j = lane + 32 * i;           // 0..287
        int c = j / 9;
        int k = j - c * 9;
        cp16(dst + j * 4, gbase + (size_t)c * HWS4 + k);
    }
    cp_commit();
}

__global__ __launch_bounds__(128, 5)
void gcfs_fused(const float* __restrict__ f,
                const float* __restrict__ Wp,
                const float* __restrict__ bp,
                float* __restrict__ out) {
    extern __shared__ float sm[];
    float* WpD = sm + OFF_WPD;       // WpD[d*33+c]
    float* bpS = sm + OFF_BP;

    const int t    = threadIdx.x;
    const int lane = t & 31;
    const int wid  = t >> 5;
    const int px   = lane >> 3;
    const int q8   = lane & 7;
    const int h    = blockIdx.y;
    const int wp0  = blockIdx.x * B_TW + wid * WPX;   // warp's first pixel

    float* warpS = sm + wid * WARPF;
    float* slot0 = warpS;
    float* slot1 = warpS + SLOT;

    const float4* fb4 = (const float4*)f;
    const size_t base4 = ((size_t)h * WS + (size_t)wp0 * S_) >> 2;  // wp0%4==0

    // --- prologue staging: src0 (g0), src1 (g1) ---
    stage_tile(slot0, fb4 + (size_t)1 * CHWS4 + base4, lane);    // image 1
    stage_tile(slot1, fb4 + (size_t)2 * CHWS4 + base4, lane);    // image 2

    // ref rows straight into registers: lane owns rows c=8co+q8 at pixel px.
    // refR[co][s] (later overwritten in place by ra = ref*att).
    float refR[4][S_];
    {
        const size_t pixOff = (size_t)h * WS + (size_t)(wp0 + px) * S_;
        #pragma unroll
        for (int co = 0; co < 4; co++) {
            const float* rp = f + (size_t)(co * 8 + q8) * HWS + pixOff;
            #pragma unroll
            for (int s = 0; s < S_; s++) refR[co][s] = __ldg(rp + s);
        }
    }

    // Wp (stride-33) + bp, L2-hot plain loads
    for (int i = t; i < C_ * C_; i += 128) {
        int d = i >> 5, c = i & 31;
        WpD[d * 33 + c] = Wp[i];
    }
    if (t < C_) bpS[t] = bp[t];

    __syncthreads();     // WpD/bp visible (the ONLY block barrier)

    // ===== warp-local attention (registers + shfl; no smem scratch) =====
    // Stage 1: p4[d] = sum_c Wp[d,c]*ref[c,px,4] + bp[d]; lane holds d=8co+q8
    float p4[4];
    #pragma unroll
    for (int co = 0; co < 4; co++) p4[co] = bpS[co * 8 + q8];
    #pragma unroll
    for (int c = 0; c < C_; c++) {
        // ref[c][px][4] lives in lane (px, c&7), reg refR[c>>3][4]
        float rc = __shfl_sync(0xFFFFFFFFu, refR[c >> 3][4], (px << 3) | (c & 7));
        #pragma unroll
        for (int co = 0; co < 4; co++)
            p4[co] += WpD[(co * 8 + q8) * 33 + c] * rc;
    }

    // k = p4 . bp  (octet reduce)
    float kk = 0.f;
    #pragma unroll
    for (int co = 0; co < 4; co++) kk += p4[co] * bpS[co * 8 + q8];
    kk += __shfl_xor_sync(0xFFFFFFFFu, kk, 1);
    kk += __shfl_xor_sync(0xFFFFFFFFu, kk, 2);
    kk += __shfl_xor_sync(0xFFFFFFFFu, kk, 4);

    // Stage 2: u[c] = sum_d Wp[d,c]*p4[px][d]; lane holds c=8co+q8
    float u[4] = {0.f, 0.f, 0.f, 0.f};
    #pragma unroll
    for (int d = 0; d < C_; d++) {
        // p4[px][d] lives in lane (px, d&7), reg p4[d>>3]
        float pd = __shfl_sync(0xFFFFFFFFu, p4[d >> 3], (px << 3) | (d & 7));
        #pragma unroll
        for (int co = 0; co < 4; co++)
            u[co] += WpD[d * 33 + co * 8 + q8] * pd;
    }

    // Stage 3: logits + softmax (redundant across octet lanes)
    float lg[S_];
    #pragma unroll
    for (int s = 0; s < S_; s++) {
        float part = 0.f;
        #pragma unroll
        for (int co = 0; co < 4; co++)
            part += u[co] * refR[co][s];
        part += __shfl_xor_sync(0xFFFFFFFFu, part, 1);
        part += __shfl_xor_sync(0xFFFFFFFFu, part, 2);
        part += __shfl_xor_sync(0xFFFFFFFFu, part, 4);
        lg[s] = (part + kk) * 0.17677669529663687f;    // 1/sqrt(32)
    }
    float mx = lg[0];
    #pragma unroll
    for (int s = 1; s < S_; s++) mx = fmaxf(mx, lg[s]);
    float sum = 0.f;
    #pragma unroll
    for (int s = 0; s < S_; s++) { lg[s] = expf(lg[s] - mx); sum += lg[s]; }
    float inv = 1.f / sum;

    // ra overwrites refR in place: refR[co][s] *= att[s]
    #pragma unroll
    for (int s = 0; s < S_; s++) {
        float a = lg[s] * inv;
        #pragma unroll
        for (int co = 0; co < 4; co++)
            refR[co][s] *= a;
    }

    // ===== warp-autonomous main loop, depth-2 ring (no block barriers) =====
    const size_t outPix = (size_t)h * W_ + wp0 + px;
    const int ghalf = q8 >> 2;              // group half within co
    const bool storer = (q8 & 3) == 0;      // lanes q8 in {0,4} store

    #pragma unroll 1
    for (int n = 0; n < NSRC; n++) {
        // groups: src0=g0, src1=g1, refill end of iter m = group m+2.
        // need group n complete; pending after = 1 for n<=6, 0 at n=7.
        if (n <= 6) cp_wait1(); else cp_wait0();

        const float* sb = ((n & 1) ? slot1 : slot0) + q8 * CROW + px * S_;
        float acc[4];
        #pragma unroll
        for (int co = 0; co < 4; co++) {
            float a = 0.f;
            #pragma unroll
            for (int s = 0; s < S_; s++)
                a += refR[co][s] * sb[co * 8 * CROW + s];
            acc[co] = a;
        }
        #pragma unroll
        for (int co = 0; co < 4; co++) {
            acc[co] += __shfl_xor_sync(0xFFFFFFFFu, acc[co], 1);
            acc[co] += __shfl_xor_sync(0xFFFFFFFFu, acc[co], 2);
        }
        if (storer) {
            #pragma unroll
            for (int co = 0; co < 4; co++)
                out[((size_t)(n * G_ + 2 * co + ghalf)) * (H_ * W_) + outPix] = acc[co];
        }

        // refill the slot just consumed with src n+2 = image n+3
        if (n <= 5)
            stage_tile((n & 1) ? slot1 : slot0,
                       fb4 + (size_t)(n + 3) * CHWS4 + base4, lane);
    }
}

// ===========================================================================
extern "C" void kernel_launch(void* const* d_in, const int* in_sizes, int n_in,
                              void* d_out, int out_size) {
    const float* f  = (const float*)d_in[0];
    const float* Wp = (const float*)d_in[1];
    const float* bp = (const float*)d_in[2];
    float* out = (float*)d_out;

    cudaFuncSetAttribute(gcfs_fused,
                         cudaFuncAttributeMaxDynamicSharedMemorySize, SMEM_BYTES);
    dim3 grid(W_ / B_TW, H_);   // (16, 192)
    gcfs_fused<<<grid, 128, SMEM_BYTES>>>(f, Wp, bp, out);
}

// round 15
// speedup vs baseline: 1.0854x; 1.0854x over previous
#include <cuda_runtime.h>
#include <cstdint>

// Problem constants
#define C_    32
#define S_    9
#define H_    192
#define W_    256
#define G_    8
#define NSRC  8

#define WS    (W_*S_)        // 2304
#define HWS   (H_*WS)        // 442368
#define CHWS  (C_*HWS)       // 14155776
#define HWS4  (HWS>>2)       // 110592
#define CHWS4 (CHWS>>2)      // 3538944

// ===========================================================================
// Fused single kernel, depth-3 ring, FULLY UNROLLED main loop (static slots).
// Warp tile = 4 pixels x 32 channels. Block = 4 warps = 16 pixels.
// Ref slot recycled as ring slot 2 after warp-local attention prologue.
// Lane map: px = lane>>3 (pixel 0..3), q8 = lane&7.
// ===========================================================================
#define WPX   4
#define NW    4
#define B_TW  (WPX*NW)       // 16 pixels per block
#define CROW  36             // floats per channel per warp tile (4 px * 9)
#define SLOT  (C_*CROW)      // 1152 floats
#define WARPF (3*SLOT)       // slot0, slot1, slot2(=ref during prologue)

#define OFF_WPD (NW*WARPF)           // WpD[d*33+c] : 1056
#define OFF_BP  (OFF_WPD+1056)       // 32
#define OFF_PSC (OFF_BP+32)          // per-warp p4 transpose scratch: 4*136
#define SMEM_FLOATS (OFF_PSC + NW*136)   // 15456
#define SMEM_BYTES  (SMEM_FLOATS*4)      // 61824 B -> 3 blocks/SM

__device__ __forceinline__ void cp16(float* dst, const float4* src) {
    uint32_t s = (uint32_t)__cvta_generic_to_shared(dst);
    asm volatile("cp.async.cg.shared.global [%0], [%1], 16;\n" :: "r"(s), "l"(src));
}
__device__ __forceinline__ void cp_commit() { asm volatile("cp.async.commit_group;\n" ::); }
__device__ __forceinline__ void cp_wait2()  { asm volatile("cp.async.wait_group 2;\n" ::); }
__device__ __forceinline__ void cp_wait1()  { asm volatile("cp.async.wait_group 1;\n" ::); }
__device__ __forceinline__ void cp_wait0()  { asm volatile("cp.async.wait_group 0;\n" ::); }

// Stage one warp tile: 288 float4 (32 ch x 9 f4), 9 per lane, linear smem.
__device__ __forceinline__ void stage_tile(float* dst, const float4* gbase, int lane) {
    #pragma unroll
    for (int i = 0; i < 9; i++) {
        int j = lane + 32 * i;           // 0..287
        int c = j / 9;
        int k = j - c * 9;
        cp16(dst + j * 4, gbase + (size_t)c * HWS4 + k);
    }
    cp_commit();
}

__global__ __launch_bounds__(128)
void gcfs_fused(const float* __restrict__ f,
                const float* __restrict__ Wp,
                const float* __restrict__ bp,
                float* __restrict__ out) {
    extern __shared__ float sm[];
    float* WpD = sm + OFF_WPD;       // WpD[d*33+c]
    float* bpS = sm + OFF_BP;

    const int t    = threadIdx.x;
    const int lane = t & 31;
    const int wid  = t >> 5;
    const int px   = lane >> 3;
    const int q8   = lane & 7;
    const int h    = blockIdx.y;
    const int wp0  = blockIdx.x * B_TW + wid * WPX;   // warp's first pixel

    float* warpS = sm + wid * WARPF;
    float* slot0 = warpS;
    float* slot1 = warpS + SLOT;
    float* slot2 = warpS + 2 * SLOT;          // ref during prologue
    float* refS  = slot2;
    float* psc   = sm + OFF_PSC + wid * 136;

    const float4* fb4 = (const float4*)f;
    const size_t base4 = ((size_t)h * WS + (size_t)wp0 * S_) >> 2;  // wp0%4==0

    // --- prologue staging: ref (g0), src0 (g1), src1 (g2) ---
    stage_tile(refS,  fb4 + base4, lane);                        // image 0
    stage_tile(slot0, fb4 + (size_t)1 * CHWS4 + base4, lane);    // image 1
    stage_tile(slot1, fb4 + (size_t)2 * CHWS4 + base4, lane);    // image 2

    // Wp (stride-33) + bp, L2-hot plain loads
    for (int i = t; i < C_ * C_; i += 128) {
        int d = i >> 5, c = i & 31;
        WpD[d * 33 + c] = Wp[i];
    }
    if (t < C_) bpS[t] = bp[t];

    cp_wait2();          // own ref complete; src0/src1 still streaming
    __syncthreads();     // WpD/bp visible (the ONLY block barrier)

    // ===== warp-local attention for this warp's 4 pixels =====
    // Stage 1: p4[px][d] = sum_c Wp[d,c]*ref[c,px,4] + bp[d]; lane holds d=8co+q8
    float p4[4];
    #pragma unroll
    for (int co = 0; co < 4; co++) p4[co] = bpS[co * 8 + q8];
    #pragma unroll
    for (int c = 0; c < C_; c++) {
        float rc = refS[c * CROW + px * S_ + 4];       // 4-addr multicast
        #pragma unroll
        for (int co = 0; co < 4; co++)
            p4[co] += WpD[(co * 8 + q8) * 33 + c] * rc;
    }

    // k[px] = p4 . bp  (octet reduce)
    float kk = 0.f;
    #pragma unroll
    for (int co = 0; co < 4; co++) kk += p4[co] * bpS[co * 8 + q8];
    kk += __shfl_xor_sync(0xFFFFFFFFu, kk, 1);
    kk += __shfl_xor_sync(0xFFFFFFFFu, kk, 2);
    kk += __shfl_xor_sync(0xFFFFFFFFu, kk, 4);

    // transpose p4 through per-warp scratch
    #pragma unroll
    for (int co = 0; co < 4; co++)
        psc[px * 33 + co * 8 + q8] = p4[co];
    __syncwarp();

    // Stage 2: u'[px][c] = sum_d Wp[d,c]*p4[px][d]; lane holds c=8co+q8
    float u[4] = {0.f, 0.f, 0.f, 0.f};
    #pragma unroll
    for (int d = 0; d < C_; d++) {
        float pd = psc[px * 33 + d];                   // multicast
        #pragma unroll
        for (int co = 0; co < 4; co++)
            u[co] += WpD[d * 33 + co * 8 + q8] * pd;
    }

    // Stage 3: logits + softmax (redundant across octet lanes)
    float lg[S_];
    #pragma unroll
    for (int s = 0; s < S_; s++) {
        float part = 0.f;
        #pragma unroll
        for (int co = 0; co < 4; co++)
            part += u[co] * refS[(co * 8 + q8) * CROW + px * S_ + s];
        part += __shfl_xor_sync(0xFFFFFFFFu, part, 1);
        part += __shfl_xor_sync(0xFFFFFFFFu, part, 2);
        part += __shfl_xor_sync(0xFFFFFFFFu, part, 4);
        lg[s] = (part + kk) * 0.17677669529663687f;    // 1/sqrt(32)
    }
    float mx = lg[0];
    #pragma unroll
    for (int s = 1; s < S_; s++) mx = fmaxf(mx, lg[s]);
    float sum = 0.f;
    #pragma unroll
    for (int s = 0; s < S_; s++) { lg[s] = expf(lg[s] - mx); sum += lg[s]; }
    float inv = 1.f / sum;

    // ra[co][s] = ref[8co+q8][px][s] * att[px][s]  — ref fully into registers
    float ra[4][S_];
    #pragma unroll
    for (int co = 0; co < 4; co++) {
        #pragma unroll
        for (int s = 0; s < S_; s++)
            ra[co][s] = refS[(co * 8 + q8) * CROW + px * S_ + s] * (lg[s] * inv);
    }

    // ref slot dead -> recycle as ring slot 2: stage src2 (image 3), group 3
    stage_tile(slot2, fb4 + (size_t)3 * CHWS4 + base4, lane);

    // ===== warp-autonomous main loop, depth-3, FULLY UNROLLED =====
    const size_t outPix = (size_t)h * W_ + wp0 + px;
    const int ghalf = q8 >> 2;              // group half within co
    const bool storer = (q8 & 3) == 0;      // lanes q8 in {0,4} store

    #pragma unroll
    for (int n = 0; n < NSRC; n++) {
        // groups: ref=0, src k = group k+1 (k<=2), refill end of iter m = group m+4.
        // wait for group n+1; pending = 2 for n<=5, 1 at n=6, 0 at n=7.
        if (n <= 5) cp_wait2();
        else if (n == 6) cp_wait1();
        else cp_wait0();

        // n is compile-time after unroll: slot pointer folds statically
        float* sbase = (n % 3 == 0) ? slot0 : ((n % 3 == 1) ? slot1 : slot2);
        const float* sb = sbase + q8 * CROW + px * S_;

        float acc[4];
        #pragma unroll
        for (int co = 0; co < 4; co++) {
            float a = 0.f;
            #pragma unroll
            for (int s = 0; s < S_; s++)
                a += ra[co][s] * sb[co * 8 * CROW + s];
            acc[co] = a;
        }
        #pragma unroll
        for (int co = 0; co < 4; co++) {
            acc[co] += __shfl_xor_sync(0xFFFFFFFFu, acc[co], 1);
            acc[co] += __shfl_xor_sync(0xFFFFFFFFu, acc[co], 2);
        }
        if (storer) {
            #pragma unroll
            for (int co = 0; co < 4; co++)
                out[((size_t)(n * G_ + 2 * co + ghalf)) * (H_ * W_) + outPix] = acc[co];
        }

        // refill the slot just consumed with src n+3 = image n+4
        if (n <= 4)
            stage_tile(sbase, fb4 + (size_t)(n + 4) * CHWS4 + base4, lane);
    }
}

// ===========================================================================
extern "C" void kernel_launch(void* const* d_in, const int* in_sizes, int n_in,
                              void* d_out, int out_size) {
    const float* f  = (const float*)d_in[0];
    const float* Wp = (const float*)d_in[1];
    const float* bp = (const float*)d_in[2];
    float* out = (float*)d_out;

    cudaFuncSetAttribute(gcfs_fused,
                         cudaFuncAttributeMaxDynamicSharedMemorySize, SMEM_BYTES);
    dim3 grid(W_ / B_TW, H_);   // (16, 192)
    gcfs_fused<<<grid, 128, SMEM_BYTES>>>(f, Wp, bp, out);
}